// round 1
// baseline (speedup 1.0000x reference)
#include <cuda_runtime.h>

#define N_NODES 40000
#define N_EDGES 640000
#define D 128

// Scratch (device globals — no allocation allowed in kernel_launch)
__device__ float g_acc[N_NODES * D];   // 20 MB mean-aggregation accumulator
__device__ float g_cnt[N_NODES];       // in-degree counts
__device__ int   g_is64;               // runtime index-width flag

// ---------------------------------------------------------------------------
// Kernel 1: zero scratch + detect whether indices are int64 or int32.
// If int64 (values < 40000, non-negative), every odd 32-bit word of the first
// 64 elements is 0. For int32 random indices that's astronomically unlikely.
// ---------------------------------------------------------------------------
__global__ void zero_kernel(const int* __restrict__ src32) {
    int idx = blockIdx.x * blockDim.x + threadIdx.x;
    if (idx < (N_NODES * D) / 4)
        reinterpret_cast<float4*>(g_acc)[idx] = make_float4(0.f, 0.f, 0.f, 0.f);
    if (idx < N_NODES)
        g_cnt[idx] = 0.f;
    if (idx == 0) {
        int is64 = 1;
        #pragma unroll 4
        for (int k = 1; k < 128; k += 2) {
            if (src32[k] != 0) { is64 = 0; break; }
        }
        g_is64 = is64;
    }
}

// ---------------------------------------------------------------------------
// Kernel 2: one warp per edge. 32 lanes x float4 = 128 floats.
// msg = feat[src] * feat[dst]; vector reduction into g_acc[dst].
// ---------------------------------------------------------------------------
__global__ void __launch_bounds__(256) edge_kernel(
    const float* __restrict__ feat,
    const void*  __restrict__ src,
    const void*  __restrict__ dst)
{
    int e    = (blockIdx.x * blockDim.x + threadIdx.x) >> 5;
    int lane = threadIdx.x & 31;
    if (e >= N_EDGES) return;

    int s, d;
    if (g_is64) {
        s = (int)reinterpret_cast<const long long*>(src)[e];
        d = (int)reinterpret_cast<const long long*>(dst)[e];
    } else {
        s = reinterpret_cast<const int*>(src)[e];
        d = reinterpret_cast<const int*>(dst)[e];
    }

    float4 a = reinterpret_cast<const float4*>(feat + (size_t)s * D)[lane];
    float4 b = reinterpret_cast<const float4*>(feat + (size_t)d * D)[lane];
    float4 m = make_float4(a.x * b.x, a.y * b.y, a.z * b.z, a.w * b.w);

    float* p = g_acc + (size_t)d * D + lane * 4;
    asm volatile("red.global.add.v4.f32 [%0], {%1, %2, %3, %4};"
                 :: "l"(p), "f"(m.x), "f"(m.y), "f"(m.z), "f"(m.w)
                 : "memory");

    if (lane == 0)
        atomicAdd(&g_cnt[d], 1.0f);
}

// ---------------------------------------------------------------------------
// Kernel 3: mean + linear. out[n] = (acc[n]/max(cnt,1)) @ W^T + b.
// W transposed into smem (row stride 132 floats: 16B-aligned float4 rows,
// only 4-way STS conflict during the one-time transpose).
// 256 threads / 8 warps; each warp computes 4 rows; lane owns 4 output cols.
// ---------------------------------------------------------------------------
#define WT_STRIDE 132

__global__ void __launch_bounds__(256) gemm_kernel(
    const float* __restrict__ W,
    const float* __restrict__ b,
    float* __restrict__ out)
{
    extern __shared__ float smem[];
    float* Wt = smem;                      // 128 * 132 floats
    float* bs = smem + D * WT_STRIDE;      // 128 floats (16B-aligned: 67584 B)

    int tid = threadIdx.x;
    for (int idx = tid; idx < D * D; idx += blockDim.x) {
        int o = idx >> 7;
        int i = idx & 127;
        Wt[i * WT_STRIDE + o] = W[idx];
    }
    if (tid < D) bs[tid] = b[tid];
    __syncthreads();

    int warp = tid >> 5;
    int lane = tid & 31;
    int r0 = (blockIdx.x * 8 + warp) * 4;  // 1250 blocks * 8 warps * 4 rows = 40000

    // Load + normalize 4 rows; lane holds elements [lane*4 .. lane*4+3] of each.
    float4 x4[4];
    #pragma unroll
    for (int j = 0; j < 4; ++j) {
        int r = r0 + j;
        float inv = 1.0f / fmaxf(g_cnt[r], 1.0f);
        float4 v = reinterpret_cast<const float4*>(g_acc + (size_t)r * D)[lane];
        x4[j] = make_float4(v.x * inv, v.y * inv, v.z * inv, v.w * inv);
    }

    float4 acc[4];
    #pragma unroll
    for (int j = 0; j < 4; ++j) acc[j] = make_float4(0.f, 0.f, 0.f, 0.f);

    for (int i4 = 0; i4 < 32; ++i4) {
        #pragma unroll
        for (int c = 0; c < 4; ++c) {
            int i = i4 * 4 + c;
            float4 w = *reinterpret_cast<const float4*>(&Wt[i * WT_STRIDE + lane * 4]);
            #pragma unroll
            for (int j = 0; j < 4; ++j) {
                float src_val = (c == 0) ? x4[j].x :
                                (c == 1) ? x4[j].y :
                                (c == 2) ? x4[j].z : x4[j].w;
                float xv = __shfl_sync(0xffffffffu, src_val, i4);
                acc[j].x = fmaf(xv, w.x, acc[j].x);
                acc[j].y = fmaf(xv, w.y, acc[j].y);
                acc[j].z = fmaf(xv, w.z, acc[j].z);
                acc[j].w = fmaf(xv, w.w, acc[j].w);
            }
        }
    }

    float4 b4 = reinterpret_cast<const float4*>(bs)[lane];
    #pragma unroll
    for (int j = 0; j < 4; ++j) {
        float4 o = make_float4(acc[j].x + b4.x, acc[j].y + b4.y,
                               acc[j].z + b4.z, acc[j].w + b4.w);
        reinterpret_cast<float4*>(out + (size_t)(r0 + j) * D)[lane] = o;
    }
}

// ---------------------------------------------------------------------------
extern "C" void kernel_launch(void* const* d_in, const int* in_sizes, int n_in,
                              void* d_out, int out_size) {
    const float* feat = (const float*)d_in[0];
    const void*  src  = d_in[1];
    const void*  dst  = d_in[2];
    const float* W    = (const float*)d_in[3];
    const float* b    = (const float*)d_in[4];
    float*       out  = (float*)d_out;

    const int smem_bytes = (D * WT_STRIDE + D) * sizeof(float);  // 68096
    cudaFuncSetAttribute(gemm_kernel,
                         cudaFuncAttributeMaxDynamicSharedMemorySize, smem_bytes);

    // 1) zero scratch + detect index width
    zero_kernel<<<(N_NODES * D / 4 + 255) / 256, 256>>>((const int*)src);

    // 2) per-edge message + scatter-reduce (1 warp per edge)
    edge_kernel<<<(N_EDGES * 32 + 255) / 256, 256>>>(feat, src, dst);

    // 3) mean + linear
    gemm_kernel<<<N_NODES / 32, 256, smem_bytes>>>(W, b, out);
}

// round 2
// speedup vs baseline: 1.1014x; 1.1014x over previous
#include <cuda_runtime.h>

#define N_NODES 40000
#define N_EDGES 640000
#define D 128
#define WT_STRIDE 132

// Scratch (device globals — no allocation allowed)
__device__ float g_acc[N_NODES * D];   // 20 MB: sum of feat[src] per dst
__device__ float g_cnt[N_NODES];       // in-degree counts

// ---------------------------------------------------------------------------
// Edge kernel: 4 edges per warp. Factored form — only gathers feat[src] and
// scatter-adds it into g_acc[dst]; the feat[dst] elementwise factor is applied
// later in the GEMM kernel (feat[d] is constant across a destination's edges).
// ---------------------------------------------------------------------------
__global__ void __launch_bounds__(256) edge_kernel(
    const float* __restrict__ feat,
    const void*  __restrict__ src,
    const void*  __restrict__ dst)
{
    int wid  = (blockIdx.x * blockDim.x + threadIdx.x) >> 5;
    int lane = threadIdx.x & 31;
    int e0   = wid * 4;
    if (e0 >= N_EDGES) return;

    // int64 vs int32 index detection (warp-uniform, L1-hit broadcast loads).
    // int64 indices < 40000 have zero odd 32-bit words; four random int32
    // indices all being 0 has probability ~4e-19.
    const int* s32 = (const int*)src;
    const int* d32 = (const int*)dst;
    bool is64 = ((s32[1] | s32[3] | s32[5] | s32[7]) == 0);

    int s[4], d[4];
    #pragma unroll
    for (int q = 0; q < 4; ++q) {
        if (is64) {
            s[q] = (int)reinterpret_cast<const long long*>(src)[e0 + q];
            d[q] = (int)reinterpret_cast<const long long*>(dst)[e0 + q];
        } else {
            s[q] = s32[e0 + q];
            d[q] = d32[e0 + q];
        }
    }

    // Batch the 4 gathers (MLP=4) before the REDs.
    float4 a[4];
    #pragma unroll
    for (int q = 0; q < 4; ++q)
        a[q] = reinterpret_cast<const float4*>(feat + (size_t)s[q] * D)[lane];

    #pragma unroll
    for (int q = 0; q < 4; ++q) {
        float* p = g_acc + (size_t)d[q] * D + lane * 4;
        asm volatile("red.global.add.v4.f32 [%0], {%1, %2, %3, %4};"
                     :: "l"(p), "f"(a[q].x), "f"(a[q].y), "f"(a[q].z), "f"(a[q].w)
                     : "memory");
    }

    // One count-increment per edge, spread across lanes 0..3.
    #pragma unroll
    for (int q = 0; q < 4; ++q) {
        if (lane == q)
            asm volatile("red.global.add.f32 [%0], %1;"
                         :: "l"(g_cnt + d[q]), "f"(1.0f) : "memory");
    }
}

// ---------------------------------------------------------------------------
// GEMM kernel: x[n] = feat[n] * g_acc[n] / max(cnt,1);  out = x @ W^T + b.
// W transposed into smem (stride 132 floats). 8 warps/block, 4 rows/warp,
// lane owns 4 output cols = 2 packed f32x2 accumulators per row.
// Inner loop uses Blackwell fma.rn.f32x2 (2x fp32 FMA rate).
// ---------------------------------------------------------------------------
__global__ void __launch_bounds__(256) gemm_kernel(
    const float* __restrict__ feat,
    const float* __restrict__ W,
    const float* __restrict__ b,
    float* __restrict__ out)
{
    extern __shared__ float smem[];
    float* Wt = smem;                      // 128 * 132 floats
    float* bs = smem + D * WT_STRIDE;      // 128 floats

    int tid = threadIdx.x;
    for (int idx = tid; idx < D * D; idx += 256) {
        int o = idx >> 7;
        int i = idx & 127;
        Wt[i * WT_STRIDE + o] = W[idx];
    }
    if (tid < D) bs[tid] = b[tid];
    __syncthreads();

    int warp = tid >> 5;
    int lane = tid & 31;
    int r0 = (blockIdx.x * 8 + warp) * 4;   // 1250 blocks * 32 rows = 40000

    // Load rows: x = feat * acc * (1/max(cnt,1)); lane holds cols [lane*4,+4).
    float4 x4[4];
    #pragma unroll
    for (int j = 0; j < 4; ++j) {
        int r = r0 + j;
        float inv = 1.0f / fmaxf(g_cnt[r], 1.0f);
        float4 va = reinterpret_cast<const float4*>(g_acc + (size_t)r * D)[lane];
        float4 vf = reinterpret_cast<const float4*>(feat  + (size_t)r * D)[lane];
        x4[j] = make_float4(va.x * vf.x * inv, va.y * vf.y * inv,
                            va.z * vf.z * inv, va.w * vf.w * inv);
    }

    unsigned long long acc0[4] = {0, 0, 0, 0};   // cols lane*4+0,1 packed
    unsigned long long acc1[4] = {0, 0, 0, 0};   // cols lane*4+2,3 packed

    unsigned wt_base = (unsigned)__cvta_generic_to_shared(Wt) + lane * 16;

    for (int i4 = 0; i4 < 32; ++i4) {
        #pragma unroll
        for (int c = 0; c < 4; ++c) {
            int i = i4 * 4 + c;
            unsigned long long wlo, whi;
            asm volatile("ld.shared.v2.u64 {%0, %1}, [%2];"
                         : "=l"(wlo), "=l"(whi)
                         : "r"(wt_base + i * (WT_STRIDE * 4)));
            #pragma unroll
            for (int j = 0; j < 4; ++j) {
                float sv = (c == 0) ? x4[j].x :
                           (c == 1) ? x4[j].y :
                           (c == 2) ? x4[j].z : x4[j].w;
                float xv = __shfl_sync(0xffffffffu, sv, i4);
                unsigned long long xp;
                asm("mov.b64 %0, {%1, %1};" : "=l"(xp) : "f"(xv));
                asm("fma.rn.f32x2 %0, %1, %2, %0;" : "+l"(acc0[j]) : "l"(xp), "l"(wlo));
                asm("fma.rn.f32x2 %0, %1, %2, %0;" : "+l"(acc1[j]) : "l"(xp), "l"(whi));
            }
        }
    }

    float4 b4 = reinterpret_cast<const float4*>(bs)[lane];
    #pragma unroll
    for (int j = 0; j < 4; ++j) {
        float l0, l1, h0, h1;
        asm("mov.b64 {%0, %1}, %2;" : "=f"(l0), "=f"(l1) : "l"(acc0[j]));
        asm("mov.b64 {%0, %1}, %2;" : "=f"(h0), "=f"(h1) : "l"(acc1[j]));
        float4 o = make_float4(l0 + b4.x, l1 + b4.y, h0 + b4.z, h1 + b4.w);
        reinterpret_cast<float4*>(out + (size_t)(r0 + j) * D)[lane] = o;
    }
}

// ---------------------------------------------------------------------------
extern "C" void kernel_launch(void* const* d_in, const int* in_sizes, int n_in,
                              void* d_out, int out_size) {
    const float* feat = (const float*)d_in[0];
    const void*  src  = d_in[1];
    const void*  dst  = d_in[2];
    const float* W    = (const float*)d_in[3];
    const float* b    = (const float*)d_in[4];
    float*       out  = (float*)d_out;

    void* acc_ptr = nullptr;
    void* cnt_ptr = nullptr;
    cudaGetSymbolAddress(&acc_ptr, g_acc);
    cudaGetSymbolAddress(&cnt_ptr, g_cnt);

    const int smem_bytes = (D * WT_STRIDE + D) * sizeof(float);  // 68096
    cudaFuncSetAttribute(gemm_kernel,
                         cudaFuncAttributeMaxDynamicSharedMemorySize, smem_bytes);

    // 1) zero scratch via memset nodes (cheaper than a kernel)
    cudaMemsetAsync(acc_ptr, 0, sizeof(float) * N_NODES * D);
    cudaMemsetAsync(cnt_ptr, 0, sizeof(float) * N_NODES);

    // 2) per-edge gather + scatter-reduce (factored: only feat[src]), 4 edges/warp
    edge_kernel<<<N_EDGES / 32, 256>>>(feat, src, dst);

    // 3) fused mean * feat[dst] + linear (f32x2 packed math)
    gemm_kernel<<<N_NODES / 32, 256, smem_bytes>>>(feat, W, b, out);
}

// round 3
// speedup vs baseline: 1.2178x; 1.1057x over previous
#include <cuda_runtime.h>

#define N_NODES 40000
#define N_EDGES 640000
#define D 128
#define BM 128
#define BK 32
#define XS_STRIDE 132

// Scratch (device globals — no allocation allowed)
__device__ float g_acc[N_NODES * D];   // 20 MB: sum of feat[src] per dst
__device__ float g_cnt[N_NODES];       // in-degree counts

// ---------------------------------------------------------------------------
// Edge kernel (unchanged from R2 — at the LTS roofline): 4 edges per warp,
// factored form: scatter-add feat[src] into g_acc[dst]; feat[dst] factor is
// applied in the GEMM kernel.
// ---------------------------------------------------------------------------
__global__ void __launch_bounds__(256) edge_kernel(
    const float* __restrict__ feat,
    const void*  __restrict__ src,
    const void*  __restrict__ dst)
{
    int wid  = (blockIdx.x * blockDim.x + threadIdx.x) >> 5;
    int lane = threadIdx.x & 31;
    int e0   = wid * 4;
    if (e0 >= N_EDGES) return;

    const int* s32 = (const int*)src;
    const int* d32 = (const int*)dst;
    bool is64 = ((s32[1] | s32[3] | s32[5] | s32[7]) == 0);

    int s[4], d[4];
    #pragma unroll
    for (int q = 0; q < 4; ++q) {
        if (is64) {
            s[q] = (int)reinterpret_cast<const long long*>(src)[e0 + q];
            d[q] = (int)reinterpret_cast<const long long*>(dst)[e0 + q];
        } else {
            s[q] = s32[e0 + q];
            d[q] = d32[e0 + q];
        }
    }

    float4 a[4];
    #pragma unroll
    for (int q = 0; q < 4; ++q)
        a[q] = reinterpret_cast<const float4*>(feat + (size_t)s[q] * D)[lane];

    #pragma unroll
    for (int q = 0; q < 4; ++q) {
        float* p = g_acc + (size_t)d[q] * D + lane * 4;
        asm volatile("red.global.add.v4.f32 [%0], {%1, %2, %3, %4};"
                     :: "l"(p), "f"(a[q].x), "f"(a[q].y), "f"(a[q].z), "f"(a[q].w)
                     : "memory");
    }

    #pragma unroll
    for (int q = 0; q < 4; ++q) {
        if (lane == q)
            asm volatile("red.global.add.f32 [%0], %1;"
                         :: "l"(g_cnt + d[q]), "f"(1.0f) : "memory");
    }
}

// ---------------------------------------------------------------------------
// GEMM kernel: out = (feat .* g_acc .* inv_cnt) @ W^T + b.
// Register-blocked 128x128 tile per block (256 threads, 8x8 per thread),
// K streamed in chunks of 32 through smem. No shuffles in the inner loop.
//   thread (tr = t>>4, tc = t&15): rows tr*8..+7, cols {tc*4..+3, 64+tc*4..+3}
//   per K-step: 2 LDS.128 (a, broadcast) + 2 LDS.128 (b) + 32 fma.f32x2
// ---------------------------------------------------------------------------
__global__ void __launch_bounds__(256) gemm_kernel(
    const float* __restrict__ feat,
    const float* __restrict__ W,
    const float* __restrict__ bias,
    float* __restrict__ out)
{
    __shared__ float xs[BK][XS_STRIDE];   // x chunk, transposed: xs[k][row]
    __shared__ float ws[BK][XS_STRIDE];   // W chunk, transposed: ws[k][ocol]
    __shared__ float invs[BM];

    const int t  = threadIdx.x;
    const int r0 = blockIdx.x * BM;       // 313 blocks cover 40064 rows
    const int tr = t >> 4;                // 0..15
    const int tc = t & 15;                // 0..15

    // Per-row 1/max(cnt,1), guarded.
    if (t < BM) {
        int r = r0 + t;
        float c = (r < N_NODES) ? g_cnt[r] : 1.0f;
        invs[t] = 1.0f / fmaxf(c, 1.0f);
    }

    unsigned long long acc[8][4];
    #pragma unroll
    for (int j = 0; j < 8; ++j)
        #pragma unroll
        for (int p = 0; p < 4; ++p) acc[j][p] = 0ULL;

    const unsigned xs_base = (unsigned)__cvta_generic_to_shared(xs);
    const unsigned ws_base = (unsigned)__cvta_generic_to_shared(ws);

    for (int kc = 0; kc < D / BK; ++kc) {
        if (kc > 0) __syncthreads();
        else __syncthreads();   // invs ready

        // Stage x chunk (computed on the fly) and W chunk, transposed.
        // idx space: 1024 = 128 rows/ocols x 8 float4-groups of k.
        #pragma unroll
        for (int i = 0; i < 4; ++i) {
            int idx = i * 256 + t;
            int r   = idx >> 3;          // 0..127
            int k4  = idx & 7;           // 0..7
            int gr  = r0 + r;
            int grc = (gr < N_NODES) ? gr : (N_NODES - 1);
            float4 f = reinterpret_cast<const float4*>(feat  + (size_t)grc * D + kc * BK)[k4];
            float4 a = reinterpret_cast<const float4*>(g_acc + (size_t)grc * D + kc * BK)[k4];
            float iv = invs[r];
            xs[k4 * 4 + 0][r] = f.x * a.x * iv;
            xs[k4 * 4 + 1][r] = f.y * a.y * iv;
            xs[k4 * 4 + 2][r] = f.z * a.z * iv;
            xs[k4 * 4 + 3][r] = f.w * a.w * iv;

            float4 w = reinterpret_cast<const float4*>(W + (size_t)r * D + kc * BK)[k4];
            ws[k4 * 4 + 0][r] = w.x;
            ws[k4 * 4 + 1][r] = w.y;
            ws[k4 * 4 + 2][r] = w.z;
            ws[k4 * 4 + 3][r] = w.w;
        }
        __syncthreads();

        #pragma unroll 8
        for (int kk = 0; kk < BK; ++kk) {
            // a: 8 row-values (2 LDS.128, 4 distinct addrs/warp -> broadcast)
            float4 a0, a1;
            asm volatile("ld.shared.v4.f32 {%0,%1,%2,%3}, [%4];"
                         : "=f"(a0.x), "=f"(a0.y), "=f"(a0.z), "=f"(a0.w)
                         : "r"(xs_base + (kk * XS_STRIDE + tr * 8) * 4));
            asm volatile("ld.shared.v4.f32 {%0,%1,%2,%3}, [%4];"
                         : "=f"(a1.x), "=f"(a1.y), "=f"(a1.z), "=f"(a1.w)
                         : "r"(xs_base + (kk * XS_STRIDE + tr * 8 + 4) * 4));
            // b: 8 col-values as 4 packed pairs (2 LDS.v2.u64, <=2-way conflict)
            unsigned long long b0, b1, b2, b3;
            asm volatile("ld.shared.v2.u64 {%0,%1}, [%2];"
                         : "=l"(b0), "=l"(b1)
                         : "r"(ws_base + (kk * XS_STRIDE + tc * 4) * 4));
            asm volatile("ld.shared.v2.u64 {%0,%1}, [%2];"
                         : "=l"(b2), "=l"(b3)
                         : "r"(ws_base + (kk * XS_STRIDE + 64 + tc * 4) * 4));

            float av[8] = {a0.x, a0.y, a0.z, a0.w, a1.x, a1.y, a1.z, a1.w};
            #pragma unroll
            for (int j = 0; j < 8; ++j) {
                unsigned long long xp;
                asm("mov.b64 %0, {%1, %1};" : "=l"(xp) : "f"(av[j]));
                asm("fma.rn.f32x2 %0, %1, %2, %0;" : "+l"(acc[j][0]) : "l"(xp), "l"(b0));
                asm("fma.rn.f32x2 %0, %1, %2, %0;" : "+l"(acc[j][1]) : "l"(xp), "l"(b1));
                asm("fma.rn.f32x2 %0, %1, %2, %0;" : "+l"(acc[j][2]) : "l"(xp), "l"(b2));
                asm("fma.rn.f32x2 %0, %1, %2, %0;" : "+l"(acc[j][3]) : "l"(xp), "l"(b3));
            }
        }
    }

    // Epilogue: + bias, store (guarded).
    float4 bA = *reinterpret_cast<const float4*>(bias + tc * 4);
    float4 bB = *reinterpret_cast<const float4*>(bias + 64 + tc * 4);
    #pragma unroll
    for (int j = 0; j < 8; ++j) {
        int r = r0 + tr * 8 + j;
        if (r >= N_NODES) break;
        float v0, v1, v2, v3;
        asm("mov.b64 {%0, %1}, %2;" : "=f"(v0), "=f"(v1) : "l"(acc[j][0]));
        asm("mov.b64 {%0, %1}, %2;" : "=f"(v2), "=f"(v3) : "l"(acc[j][1]));
        float4 oA = make_float4(v0 + bA.x, v1 + bA.y, v2 + bA.z, v3 + bA.w);
        asm("mov.b64 {%0, %1}, %2;" : "=f"(v0), "=f"(v1) : "l"(acc[j][2]));
        asm("mov.b64 {%0, %1}, %2;" : "=f"(v2), "=f"(v3) : "l"(acc[j][3]));
        float4 oB = make_float4(v0 + bB.x, v1 + bB.y, v2 + bB.z, v3 + bB.w);
        *reinterpret_cast<float4*>(out + (size_t)r * D + tc * 4)      = oA;
        *reinterpret_cast<float4*>(out + (size_t)r * D + 64 + tc * 4) = oB;
    }
}

// ---------------------------------------------------------------------------
extern "C" void kernel_launch(void* const* d_in, const int* in_sizes, int n_in,
                              void* d_out, int out_size) {
    const float* feat = (const float*)d_in[0];
    const void*  src  = d_in[1];
    const void*  dst  = d_in[2];
    const float* W    = (const float*)d_in[3];
    const float* b    = (const float*)d_in[4];
    float*       out  = (float*)d_out;

    void* acc_ptr = nullptr;
    void* cnt_ptr = nullptr;
    cudaGetSymbolAddress(&acc_ptr, g_acc);
    cudaGetSymbolAddress(&cnt_ptr, g_cnt);

    cudaMemsetAsync(acc_ptr, 0, sizeof(float) * N_NODES * D);
    cudaMemsetAsync(cnt_ptr, 0, sizeof(float) * N_NODES);

    edge_kernel<<<N_EDGES / 32, 256>>>(feat, src, dst);

    gemm_kernel<<<(N_NODES + BM - 1) / BM, 256>>>(feat, W, b, out);
}

// round 4
// speedup vs baseline: 1.2458x; 1.0230x over previous
#include <cuda_runtime.h>

#define N_NODES 40000
#define N_EDGES 640000
#define D 128
#define BM 64
#define BK 32
#define XS_STRIDE 36
#define WS_STRIDE 128

// Scratch (device globals — no allocation allowed)
__device__ float g_acc[N_NODES * D];   // 20 MB: sum of feat[src] per dst
__device__ float g_cnt[N_NODES];       // in-degree counts
__device__ float g_wt[D * D];          // W^T: g_wt[i*D + o] = W[o*D + i]

// ---------------------------------------------------------------------------
// One-time W transpose (64 KB through L2, ~2us).
// ---------------------------------------------------------------------------
__global__ void wtrans_kernel(const float* __restrict__ W) {
    int idx = blockIdx.x * 256 + threadIdx.x;   // 0..16383
    int o = idx >> 7, i = idx & 127;
    g_wt[i * D + o] = W[idx];
}

// ---------------------------------------------------------------------------
// Edge kernel (unchanged — at the LTS byte roofline): 4 edges/warp, factored:
// scatter-add feat[src] into g_acc[dst]; feat[dst] factor applied in the GEMM.
// ---------------------------------------------------------------------------
__global__ void __launch_bounds__(256) edge_kernel(
    const float* __restrict__ feat,
    const void*  __restrict__ src,
    const void*  __restrict__ dst)
{
    int wid  = (blockIdx.x * blockDim.x + threadIdx.x) >> 5;
    int lane = threadIdx.x & 31;
    int e0   = wid * 4;
    if (e0 >= N_EDGES) return;

    const int* s32 = (const int*)src;
    const int* d32 = (const int*)dst;
    bool is64 = ((s32[1] | s32[3] | s32[5] | s32[7]) == 0);

    int s[4], d[4];
    #pragma unroll
    for (int q = 0; q < 4; ++q) {
        if (is64) {
            s[q] = (int)reinterpret_cast<const long long*>(src)[e0 + q];
            d[q] = (int)reinterpret_cast<const long long*>(dst)[e0 + q];
        } else {
            s[q] = s32[e0 + q];
            d[q] = d32[e0 + q];
        }
    }

    float4 a[4];
    #pragma unroll
    for (int q = 0; q < 4; ++q)
        a[q] = reinterpret_cast<const float4*>(feat + (size_t)s[q] * D)[lane];

    #pragma unroll
    for (int q = 0; q < 4; ++q) {
        float* p = g_acc + (size_t)d[q] * D + lane * 4;
        asm volatile("red.global.add.v4.f32 [%0], {%1, %2, %3, %4};"
                     :: "l"(p), "f"(a[q].x), "f"(a[q].y), "f"(a[q].z), "f"(a[q].w)
                     : "memory");
    }

    #pragma unroll
    for (int q = 0; q < 4; ++q) {
        if (lane == q)
            asm volatile("red.global.add.f32 [%0], %1;"
                         :: "l"(g_cnt + d[q]), "f"(1.0f) : "memory");
    }
}

// ---------------------------------------------------------------------------
// GEMM: out = (feat .* g_acc .* inv_cnt) @ W^T + b.
// 64x128 tile/block, 256 threads, 4 rows x 8 cols/thread.
// Register-prefetched, double-buffered smem pipeline; 1 sync per K-chunk.
// ---------------------------------------------------------------------------
__global__ void __launch_bounds__(256) gemm_kernel(
    const float* __restrict__ feat,
    const float* __restrict__ bias,
    float* __restrict__ out)
{
    extern __shared__ float smem[];
    // xs[2][BM][XS_STRIDE] then ws[2][BK][WS_STRIDE]
    float* xs = smem;                                  // 2*64*36  = 4608 floats
    float* ws = smem + 2 * BM * XS_STRIDE;             // 2*32*128 = 8192 floats

    const int t  = threadIdx.x;
    const int r0 = blockIdx.x * BM;     // 625 blocks * 64 = 40000 exact
    const int tr = t >> 4;              // 0..15 -> rows tr*4..+3
    const int tc = t & 15;              // cols tc*4..+3 and 64+tc*4..+3

    // x staging: thread owns (row=t>>3, k4=t&7) and (row+32, k4)
    const int xrow = t >> 3;
    const int xk4  = t & 7;
    // w staging: thread owns k = (t>>5)+8m, oc4 = t&31, m=0..3
    const int wk   = t >> 5;
    const int woc4 = t & 31;

    const float inv0 = 1.0f / fmaxf(g_cnt[r0 + xrow], 1.0f);
    const float inv1 = 1.0f / fmaxf(g_cnt[r0 + xrow + 32], 1.0f);

    float4 fx0, fa0, fx1, fa1, fw0, fw1, fw2, fw3;

    // ---- prefetch chunk 0
    {
        const float* fp = feat  + (size_t)(r0 + xrow) * D + xk4 * 4;
        const float* ap = g_acc + (size_t)(r0 + xrow) * D + xk4 * 4;
        fx0 = *(const float4*)fp;  fx1 = *(const float4*)(fp + 32 * D);
        fa0 = *(const float4*)ap;  fa1 = *(const float4*)(ap + 32 * D);
        const float* wp = g_wt + (size_t)(wk) * D + woc4 * 4;
        fw0 = *(const float4*)wp;
        fw1 = *(const float4*)(wp + 8 * D);
        fw2 = *(const float4*)(wp + 16 * D);
        fw3 = *(const float4*)(wp + 24 * D);
    }

    unsigned long long acc[4][4];
    #pragma unroll
    for (int j = 0; j < 4; ++j)
        #pragma unroll
        for (int p = 0; p < 4; ++p) acc[j][p] = 0ULL;

    for (int kc = 0; kc < D / BK; ++kc) {
        const int buf = kc & 1;
        float* xb = xs + buf * BM * XS_STRIDE;
        float* wb = ws + buf * BK * WS_STRIDE;

        // ---- store prefetched chunk into smem
        *(float4*)&xb[xrow * XS_STRIDE + xk4 * 4] =
            make_float4(fx0.x * fa0.x * inv0, fx0.y * fa0.y * inv0,
                        fx0.z * fa0.z * inv0, fx0.w * fa0.w * inv0);
        *(float4*)&xb[(xrow + 32) * XS_STRIDE + xk4 * 4] =
            make_float4(fx1.x * fa1.x * inv1, fx1.y * fa1.y * inv1,
                        fx1.z * fa1.z * inv1, fx1.w * fa1.w * inv1);
        *(float4*)&wb[(wk +  0) * WS_STRIDE + woc4 * 4] = fw0;
        *(float4*)&wb[(wk +  8) * WS_STRIDE + woc4 * 4] = fw1;
        *(float4*)&wb[(wk + 16) * WS_STRIDE + woc4 * 4] = fw2;
        *(float4*)&wb[(wk + 24) * WS_STRIDE + woc4 * 4] = fw3;
        __syncthreads();

        // ---- prefetch next chunk (hidden under compute below)
        if (kc < D / BK - 1) {
            const int ko = (kc + 1) * BK;
            const float* fp = feat  + (size_t)(r0 + xrow) * D + ko + xk4 * 4;
            const float* ap = g_acc + (size_t)(r0 + xrow) * D + ko + xk4 * 4;
            fx0 = *(const float4*)fp;  fx1 = *(const float4*)(fp + 32 * D);
            fa0 = *(const float4*)ap;  fa1 = *(const float4*)(ap + 32 * D);
            const float* wp = g_wt + (size_t)(ko + wk) * D + woc4 * 4;
            fw0 = *(const float4*)wp;
            fw1 = *(const float4*)(wp + 8 * D);
            fw2 = *(const float4*)(wp + 16 * D);
            fw3 = *(const float4*)(wp + 24 * D);
        }

        // ---- compute 32 K-steps from smem
        #pragma unroll 8
        for (int kk = 0; kk < BK; ++kk) {
            float a0 = xb[(tr * 4 + 0) * XS_STRIDE + kk];
            float a1 = xb[(tr * 4 + 1) * XS_STRIDE + kk];
            float a2 = xb[(tr * 4 + 2) * XS_STRIDE + kk];
            float a3 = xb[(tr * 4 + 3) * XS_STRIDE + kk];

            ulonglong2 wA = *(const ulonglong2*)&wb[kk * WS_STRIDE + tc * 4];
            ulonglong2 wB = *(const ulonglong2*)&wb[kk * WS_STRIDE + 64 + tc * 4];

            float av[4] = {a0, a1, a2, a3};
            #pragma unroll
            for (int j = 0; j < 4; ++j) {
                unsigned long long xp;
                asm("mov.b64 %0, {%1, %1};" : "=l"(xp) : "f"(av[j]));
                asm("fma.rn.f32x2 %0, %1, %2, %0;" : "+l"(acc[j][0]) : "l"(xp), "l"(wA.x));
                asm("fma.rn.f32x2 %0, %1, %2, %0;" : "+l"(acc[j][1]) : "l"(xp), "l"(wA.y));
                asm("fma.rn.f32x2 %0, %1, %2, %0;" : "+l"(acc[j][2]) : "l"(xp), "l"(wB.x));
                asm("fma.rn.f32x2 %0, %1, %2, %0;" : "+l"(acc[j][3]) : "l"(xp), "l"(wB.y));
            }
        }
    }

    // ---- epilogue: + bias, store (no guards: 625*64 == 40000)
    float4 bA = *(const float4*)(bias + tc * 4);
    float4 bB = *(const float4*)(bias + 64 + tc * 4);
    #pragma unroll
    for (int j = 0; j < 4; ++j) {
        int r = r0 + tr * 4 + j;
        float v0, v1, v2, v3;
        asm("mov.b64 {%0, %1}, %2;" : "=f"(v0), "=f"(v1) : "l"(acc[j][0]));
        asm("mov.b64 {%0, %1}, %2;" : "=f"(v2), "=f"(v3) : "l"(acc[j][1]));
        float4 oA = make_float4(v0 + bA.x, v1 + bA.y, v2 + bA.z, v3 + bA.w);
        asm("mov.b64 {%0, %1}, %2;" : "=f"(v0), "=f"(v1) : "l"(acc[j][2]));
        asm("mov.b64 {%0, %1}, %2;" : "=f"(v2), "=f"(v3) : "l"(acc[j][3]));
        float4 oB = make_float4(v0 + bB.x, v1 + bB.y, v2 + bB.z, v3 + bB.w);
        *(float4*)(out + (size_t)r * D + tc * 4)      = oA;
        *(float4*)(out + (size_t)r * D + 64 + tc * 4) = oB;
    }
}

// ---------------------------------------------------------------------------
extern "C" void kernel_launch(void* const* d_in, const int* in_sizes, int n_in,
                              void* d_out, int out_size) {
    const float* feat = (const float*)d_in[0];
    const void*  src  = d_in[1];
    const void*  dst  = d_in[2];
    const float* W    = (const float*)d_in[3];
    const float* b    = (const float*)d_in[4];
    float*       out  = (float*)d_out;

    void* acc_ptr = nullptr;
    void* cnt_ptr = nullptr;
    cudaGetSymbolAddress(&acc_ptr, g_acc);
    cudaGetSymbolAddress(&cnt_ptr, g_cnt);

    const int smem_bytes = (2 * BM * XS_STRIDE + 2 * BK * WS_STRIDE) * sizeof(float); // 51200
    cudaFuncSetAttribute(gemm_kernel,
                         cudaFuncAttributeMaxDynamicSharedMemorySize, smem_bytes);

    cudaMemsetAsync(acc_ptr, 0, sizeof(float) * N_NODES * D);
    cudaMemsetAsync(cnt_ptr, 0, sizeof(float) * N_NODES);

    wtrans_kernel<<<64, 256>>>(W);

    edge_kernel<<<N_EDGES / 32, 256>>>(feat, src, dst);

    gemm_kernel<<<N_NODES / BM, 256, smem_bytes>>>(feat, b, out);
}